// round 8
// baseline (speedup 1.0000x reference)
#include <cuda_runtime.h>

// Batched 12x12 complex-DFT magnitude, approx pass only.
// R7 (resubmit after infra timeout): sub2 via fma2(b, -1, a) (1 fma-pipe
// issue, exact) replacing neg+add (3 issues, 2 on alu pipe); staging tail
// peeled. Otherwise R6 structure: stage-B 7-term dot products via
// even(wre)/odd(wim) k-fold symmetry, Hermitian row mirror, f32x2
// 2-tiles-per-lane, 32 pairs x 7 rows = 224 thr, 3 blocks/SM.

typedef unsigned long long u64;

__device__ __forceinline__ u64 pk2(float lo, float hi) {
    u64 r; asm("mov.b64 %0,{%1,%2};" : "=l"(r) : "f"(lo), "f"(hi)); return r;
}
__device__ __forceinline__ void upk2(u64 v, float& lo, float& hi) {
    asm("mov.b64 {%0,%1},%2;" : "=f"(lo), "=f"(hi) : "l"(v));
}
__device__ __forceinline__ u64 fma2(u64 a, u64 b, u64 c) {
    u64 d; asm("fma.rn.f32x2 %0,%1,%2,%3;" : "=l"(d) : "l"(a), "l"(b), "l"(c)); return d;
}
__device__ __forceinline__ u64 add2(u64 a, u64 b) {
    u64 d; asm("add.rn.f32x2 %0,%1,%2;" : "=l"(d) : "l"(a), "l"(b)); return d;
}
__device__ __forceinline__ u64 mul2(u64 a, u64 b) {
    u64 d; asm("mul.rn.f32x2 %0,%1,%2;" : "=l"(d) : "l"(a), "l"(b)); return d;
}
__device__ __forceinline__ float sqrt_ap(float x) {
    float r; asm("sqrt.approx.f32 %0,%1;" : "=f"(r) : "f"(x)); return r;
}

// packed {-1.0f,-1.0f}
#define NEG1 0xBF800000BF800000ULL
// exact a - b on both lanes, single fma-pipe issue
__device__ __forceinline__ u64 sub2(u64 a, u64 b) { return fma2(b, NEG1, a); }

#define PITCH 146
#define NPAIR 32
#define NROW  7
#define NTHR  224

__global__ void __launch_bounds__(NTHR, 3)
dft_mag_kernel(const float* __restrict__ x,
               const float* __restrict__ wr,
               const float* __restrict__ wi,
               float* __restrict__ out, int size)
{
    __shared__ ulonglong2 sWA[144];    // exact stage-A weights [r*12+j]
    __shared__ ulonglong2 sLUT[12];    // distinct weights by m=(jk)%12 (row 1)
    __shared__ u64 sX[NPAIR][PITCH];   // [pair][j*12+c] f32x2

    const int t = threadIdx.x;

    if (t < 144) {
        float qa = rintf(wr[t] * 65535.0f) * (1.0f / 65536.0f);
        float qb = rintf(wi[t] * 65535.0f) * (1.0f / 65536.0f);
        ulonglong2 w; w.x = pk2(qa, qa); w.y = pk2(qb, qb);
        sWA[t] = w;
    }
    if (t < 12) {
        float qa = rintf(wr[12 + t] * 65535.0f) * (1.0f / 65536.0f);
        float qb = rintf(wi[12 + t] * 65535.0f) * (1.0f / 65536.0f);
        ulonglong2 w; w.x = pk2(qa, qa); w.y = pk2(qb, qb);
        sLUT[t] = w;
    }

    // ---- stage-in 64 tiles: 1152 pair-sets; 5 full sweeps + t<32 tail ----
    const long base4 = (long)blockIdx.x * NPAIR * 72;
    const long n4 = ((long)size * 144) >> 2;
    const float4* in4 = reinterpret_cast<const float4*>(x);
#pragma unroll
    for (int s = 0; s < 5; s++) {
        int p = s * NTHR + t;                 // < 1152 always
        int pair = p / 36, q = p % 36;
        long i0 = base4 + (long)pair * 72 + q;
        if (i0 + 36 < n4) {
            float4 v0 = in4[i0];
            float4 v1 = in4[i0 + 36];
            ulonglong2* dst = reinterpret_cast<ulonglong2*>(&sX[pair][q * 4]);
            ulonglong2 d0, d1;
            d0.x = pk2(v0.x, v1.x); d0.y = pk2(v0.y, v1.y);
            d1.x = pk2(v0.z, v1.z); d1.y = pk2(v0.w, v1.w);
            dst[0] = d0; dst[1] = d1;
        }
    }
    if (t < 32) {
        int p = 5 * NTHR + t;                 // 1120..1151
        int pair = p / 36, q = p % 36;
        long i0 = base4 + (long)pair * 72 + q;
        if (i0 + 36 < n4) {
            float4 v0 = in4[i0];
            float4 v1 = in4[i0 + 36];
            ulonglong2* dst = reinterpret_cast<ulonglong2*>(&sX[pair][q * 4]);
            ulonglong2 d0, d1;
            d0.x = pk2(v0.x, v1.x); d0.y = pk2(v0.y, v1.y);
            d1.x = pk2(v0.z, v1.z); d1.y = pk2(v0.w, v1.w);
            dst[0] = d0; dst[1] = d1;
        }
    }
    __syncthreads();

    const int pr = t / NROW;
    const int r  = t % NROW;
    const u64* xp = sX[pr];

    // ---- stage A: rt[c] = sum_j w[r][j]*x[j][c] (exact entries) ----
    u64 rt[12], it[12];
    {
        ulonglong2 w0 = sWA[r * 12];
        const ulonglong2* xr = reinterpret_cast<const ulonglong2*>(xp);
        ulonglong2 x0 = xr[0], x1 = xr[1], x2 = xr[2],
                   x3 = xr[3], x4 = xr[4], x5 = xr[5];
        u64 xv[12] = { x0.x, x0.y, x1.x, x1.y, x2.x, x2.y,
                       x3.x, x3.y, x4.x, x4.y, x5.x, x5.y };
#pragma unroll
        for (int c = 0; c < 12; c++) {
            rt[c] = mul2(w0.x, xv[c]);
            it[c] = mul2(w0.y, xv[c]);
        }
    }
#pragma unroll
    for (int j = 1; j < 12; j++) {
        ulonglong2 w = sWA[r * 12 + j];
        const ulonglong2* xr = reinterpret_cast<const ulonglong2*>(xp + j * 12);
        ulonglong2 x0 = xr[0], x1 = xr[1], x2 = xr[2],
                   x3 = xr[3], x4 = xr[4], x5 = xr[5];
        u64 xv[12] = { x0.x, x0.y, x1.x, x1.y, x2.x, x2.y,
                       x3.x, x3.y, x4.x, x4.y, x5.x, x5.y };
#pragma unroll
        for (int c = 0; c < 12; c++) {
            rt[c] = fma2(w.x, xv[c], rt[c]);
            it[c] = fma2(w.y, xv[c], it[c]);
        }
    }

    // ---- fold k/(12-k): sums (even wre) and diffs (odd wim) ----
    u64 rs[6], rd[6], is[6], id[6];
#pragma unroll
    for (int k = 1; k <= 5; k++) {
        rs[k] = add2(rt[k], rt[12 - k]);
        rd[k] = sub2(rt[k], rt[12 - k]);
        is[k] = add2(it[k], it[12 - k]);
        id[k] = sub2(it[k], it[12 - k]);
    }
    const u64 a0 = rt[0], a6 = rt[6], b0 = it[0], b6 = it[6];

    // ---- register LUT: wre[m], wim[m], m = 0..6 ----
    u64 wre[7], wim[7];
#pragma unroll
    for (int m = 0; m < 7; m++) {
        ulonglong2 w = sLUT[m];
        wre[m] = w.x; wim[m] = w.y;
    }

    // ---- stage B: 7-term dot products via symmetry ----
    float lo[12], hi[12];
#pragma unroll
    for (int c = 0; c < 12; c++) {
        const int m6 = ((6 * c) % 12 == 6) ? 6 : 0;      // compile-time
        u64 p1 = fma2(a6, wre[m6], mul2(a0, wre[0]));
        u64 p4 = fma2(b6, wre[m6], mul2(b0, wre[0]));
        u64 p2p = fma2(b6, wim[m6], mul2(b0, wim[0]));
        u64 p2n = 0;
        u64 p3p = fma2(a6, wim[m6], mul2(a0, wim[0]));
        u64 p3n = 0;
#pragma unroll
        for (int k = 1; k <= 5; k++) {
            const int mk = (k * c) % 12;                 // compile-time
            const int me = (mk <= 6) ? mk : 12 - mk;
            p1 = fma2(rs[k], wre[me], p1);
            p4 = fma2(is[k], wre[me], p4);
            if (mk == 0 || mk == 6) {
                p2p = fma2(is[k], wim[mk], p2p);
                p3p = fma2(rs[k], wim[mk], p3p);
            } else if (mk < 6) {
                p2p = fma2(id[k], wim[mk], p2p);
                p3p = fma2(rd[k], wim[mk], p3p);
            } else {
                p2n = fma2(id[k], wim[12 - mk], p2n);
                p3n = fma2(rd[k], wim[12 - mk], p3n);
            }
        }
        u64 ro = add2(sub2(p1, p2p), p2n);
        u64 io = add2(sub2(p3p, p3n), p4);
        u64 mg = fma2(ro, ro, mul2(io, io));
        float mlo, mhi; upk2(mg, mlo, mhi);
        lo[c] = sqrt_ap(mlo);
        hi[c] = sqrt_ap(mhi);
    }

    // ---- stores: row r + (r=1..5) Hermitian mirror row 12-r ----
    long item0 = (long)blockIdx.x * NPAIR * 2 + 2 * pr;
    float* tb0 = out + item0 * 144;
    float* tb1 = tb0 + 144;
    const bool full = (item0 + 1 < (long)size);
    const int  r2 = 12 - r;

    if (full) {
        float4* o0 = reinterpret_cast<float4*>(tb0 + r * 12);
        float4* o1 = reinterpret_cast<float4*>(tb1 + r * 12);
        o0[0] = make_float4(lo[0], lo[1], lo[2],  lo[3]);
        o0[1] = make_float4(lo[4], lo[5], lo[6],  lo[7]);
        o0[2] = make_float4(lo[8], lo[9], lo[10], lo[11]);
        o1[0] = make_float4(hi[0], hi[1], hi[2],  hi[3]);
        o1[1] = make_float4(hi[4], hi[5], hi[6],  hi[7]);
        o1[2] = make_float4(hi[8], hi[9], hi[10], hi[11]);
        if (r >= 1 && r <= 5) {
            float4* m0 = reinterpret_cast<float4*>(tb0 + r2 * 12);
            float4* m1 = reinterpret_cast<float4*>(tb1 + r2 * 12);
            m0[0] = make_float4(lo[0], lo[11], lo[10], lo[9]);
            m0[1] = make_float4(lo[8], lo[7],  lo[6],  lo[5]);
            m0[2] = make_float4(lo[4], lo[3],  lo[2],  lo[1]);
            m1[0] = make_float4(hi[0], hi[11], hi[10], hi[9]);
            m1[1] = make_float4(hi[8], hi[7],  hi[6],  hi[5]);
            m1[2] = make_float4(hi[4], hi[3],  hi[2],  hi[1]);
        }
    } else if (item0 < (long)size) {       // odd tail (unused at size=100000)
        float* o0 = tb0 + r * 12;
#pragma unroll
        for (int c = 0; c < 12; c++) o0[c] = lo[c];
        if (r >= 1 && r <= 5) {
            float* m0 = tb0 + r2 * 12;
            m0[0] = lo[0];
#pragma unroll
            for (int c = 1; c < 12; c++) m0[c] = lo[12 - c];
        }
    }
}

extern "C" void kernel_launch(void* const* d_in, const int* in_sizes, int n_in,
                              void* d_out, int out_size)
{
    const float* x  = (const float*)d_in[0];
    const float* wr = (const float*)d_in[1];
    const float* wi = (const float*)d_in[2];
    float* out = (float*)d_out;

    int size = in_sizes[0] / 144;
    int blocks = (size + NPAIR * 2 - 1) / (NPAIR * 2);   // 1563
    dft_mag_kernel<<<blocks, NTHR>>>(x, wr, wi, out, size);
}